// round 5
// baseline (speedup 1.0000x reference)
#include <cuda_runtime.h>

#define N_NODES 100000
#define E_MAX   3200000
#define F_XD    64
#define F_UD    128
#define F_OUTD  128
#define B_GLOB  512

#define PK_CTAS    296
#define PK_THREADS 512
#define ZCTAS      168    // CTAs doing deg-zeroing in phase 0; rest do u_proj

typedef unsigned long long ull;

__device__ float g_agg[N_NODES * F_XD];
__device__ float g_U[B_GLOB * 256];
__device__ int   g_is64;
__device__ int   g_deg[N_NODES];
__device__ int   g_rowptr[N_NODES];
__device__ int   g_cursor[N_NODES];
__device__ int   g_bsum[512];
__device__ int   g_boff[512];
__device__ uint2 g_edges[E_MAX];
__device__ unsigned g_bar_count;   // zero-init; barrier leaves it 0
__device__ unsigned g_bar_gen;     // monotonic across replays (safe)

__device__ __forceinline__ ull pack2(float a, float b) {
    ull r; asm("mov.b64 %0, {%1, %2};" : "=l"(r) : "f"(a), "f"(b)); return r;
}
__device__ __forceinline__ void ffma2(ull& d, ull a, ull b) {
    asm("fma.rn.f32x2 %0, %1, %2, %0;" : "+l"(d) : "l"(a), "l"(b));
}
__device__ __forceinline__ ull add2(ull a, ull b) {
    ull r; asm("add.rn.f32x2 %0, %1, %2;" : "=l"(r) : "l"(a), "l"(b)); return r;
}

// Software grid barrier: all PK_CTAS are co-resident (launch_bounds(512,2),
// grid=296 <= 2*148 SMs). Volatile-load spin, atomic release.
__device__ __forceinline__ void grid_barrier() {
    __syncthreads();
    __threadfence();
    if (threadIdx.x == 0) {
        unsigned gen = *(volatile unsigned*)&g_bar_gen;
        if (atomicAdd(&g_bar_count, 1u) == (unsigned)gridDim.x - 1u) {
            atomicExch(&g_bar_count, 0u);
            __threadfence();
            atomicExch(&g_bar_gen, gen + 1u);
        } else {
            while (*(volatile unsigned*)&g_bar_gen == gen) { __nanosleep(64); }
        }
        __threadfence();
    }
    __syncthreads();
}

// ---------------------------------------------------------------------------
// Persistent kernel: phase0 (zero deg + probe | u_proj), hist, scan(a,b,c),
// fill, aggregate. 6 grid barriers, 1 launch.
// ---------------------------------------------------------------------------
__global__ void __launch_bounds__(PK_THREADS, 2)
persist_kernel(const float* __restrict__ x,
               const void*  __restrict__ ei,
               const float* __restrict__ attr,
               const float* __restrict__ u,
               const float* __restrict__ WK, const float* __restrict__ bK,
               const float* __restrict__ WQ, const float* __restrict__ bQ,
               int E, int N) {
    __shared__ int ss[PK_THREADS];
    const int tid   = threadIdx.x;
    const int tid_g = blockIdx.x * PK_THREADS + tid;
    const int nt    = gridDim.x * PK_THREADS;

    // ---- Phase 0: zero deg counters (+probe) on CTAs [0,ZCTAS); u_proj on rest
    if (blockIdx.x < ZCTAS) {
        int zt = blockIdx.x * PK_THREADS + tid;
        for (int i = zt; i < N; i += ZCTAS * PK_THREADS) g_deg[i] = 0;
        if (zt == 0) {
            const long long* p = (const long long*)ei;
            long long stride = (2LL * E) / 64;
            int ok = 1;
            for (int j = 0; j < 64; j++) {
                long long v = p[(long long)j * stride];
                if (v < 0 || v >= N) { ok = 0; break; }
            }
            g_is64 = ok;
        }
    } else {
        // u_proj: 128 CTAs x 4 batch rows, threads 0..255 active
        float* su = (float*)ss;                 // [4][128] floats = 2KB
        int ub = blockIdx.x - ZCTAS;            // 0..127
        int b0 = ub * 4;
        for (int i = tid; i < 4 * F_UD; i += PK_THREADS)
            su[i] = u[(b0 + (i >> 7)) * F_UD + (i & 127)];
        __syncthreads();
        if (tid < 256) {
            int j = tid;
            const float* W   = (j < F_OUTD) ? WK : WQ;
            int          col = j & (F_OUTD - 1);
            float bias = (j < F_OUTD) ? bK[col] : bQ[col];
            float a0 = bias, a1 = bias, a2 = bias, a3 = bias;
#pragma unroll 4
            for (int k = 0; k < F_UD; k++) {
                float wv = W[(F_XD + k) * F_OUTD + col];
                a0 = fmaf(su[0 * 128 + k], wv, a0);
                a1 = fmaf(su[1 * 128 + k], wv, a1);
                a2 = fmaf(su[2 * 128 + k], wv, a2);
                a3 = fmaf(su[3 * 128 + k], wv, a3);
            }
            g_U[(b0 + 0) * 256 + j] = a0;
            g_U[(b0 + 1) * 256 + j] = a1;
            g_U[(b0 + 2) * 256 + j] = a2;
            g_U[(b0 + 3) * 256 + j] = a3;
        }
    }
    grid_barrier();

    const int is64 = g_is64;

    // ---- Phase 1: in-degree histogram
    if (!is64) {
        int n4 = E >> 2;
        const int4* d4p = (const int4*)((const int*)ei + E);
        for (int i = tid_g; i < n4; i += nt) {
            int4 d4 = d4p[i];
            atomicAdd(&g_deg[d4.x], 1);
            atomicAdd(&g_deg[d4.y], 1);
            atomicAdd(&g_deg[d4.z], 1);
            atomicAdd(&g_deg[d4.w], 1);
        }
        int tail = E & 3;
        if (tid_g < tail)
            atomicAdd(&g_deg[((const int*)ei)[E + (E - tail) + tid_g]], 1);
    } else {
        for (int e = tid_g; e < E; e += nt)
            atomicAdd(&g_deg[(int)((const long long*)ei)[E + e]], 1);
    }
    grid_barrier();

    // ---- Phase 2a: per-CTA chunk sums + block-local exclusive scan
    int chunk = (N + gridDim.x - 1) / gridDim.x;          // 338 for N=100000
    int per   = (chunk + PK_THREADS - 1) / PK_THREADS;    // 1
    if (per > 4) per = 4;                                  // defensive clamp
    int cbeg  = blockIdx.x * chunk;
    int clim  = cbeg + chunk; if (clim > N) clim = N;
    int base  = cbeg + tid * per;

    int vloc[4]; int tsum = 0;
#pragma unroll
    for (int j = 0; j < 4; j++) {
        int idx = base + j;
        int v = (j < per && idx < clim) ? g_deg[idx] : 0;
        vloc[j] = v; tsum += v;
    }
    ss[tid] = tsum;
    __syncthreads();
    for (int off = 1; off < PK_THREADS; off <<= 1) {
        int add = (tid >= off) ? ss[tid - off] : 0;
        __syncthreads();
        ss[tid] += add;
        __syncthreads();
    }
    int excl = ss[tid] - tsum;
    if (tid == PK_THREADS - 1) g_bsum[blockIdx.x] = ss[tid];
    grid_barrier();

    // ---- Phase 2b: CTA 0 scans the per-CTA totals
    if (blockIdx.x == 0) {
        int nbk = gridDim.x;
        int v = (tid < nbk) ? g_bsum[tid] : 0;
        ss[tid] = v;
        __syncthreads();
        for (int off = 1; off < PK_THREADS; off <<= 1) {
            int add = (tid >= off) ? ss[tid - off] : 0;
            __syncthreads();
            ss[tid] += add;
            __syncthreads();
        }
        if (tid < nbk) g_boff[tid] = ss[tid] - v;
    }
    grid_barrier();

    // ---- Phase 2c: write rowptr + cursor from register-held values
    {
        int run = g_boff[blockIdx.x] + excl;
#pragma unroll
        for (int j = 0; j < 4; j++) {
            int idx = base + j;
            if (j < per && idx < clim) {
                g_rowptr[idx] = run;
                g_cursor[idx] = run;
                run += vloc[j];
            }
        }
    }
    grid_barrier();

    // ---- Phase 3: bucket edges by dest
    if (!is64) {
        int n4 = E >> 2;
        const int4*   sp = (const int4*)((const int*)ei);
        const int4*   dp = (const int4*)((const int*)ei + E);
        const float4* ap = (const float4*)attr;
        for (int i = tid_g; i < n4; i += nt) {
            int4   s4 = sp[i];
            int4   d4 = dp[i];
            float4 a4 = ap[i];
            int p0 = atomicAdd(&g_cursor[d4.x], 1);
            g_edges[p0] = make_uint2((unsigned)s4.x, __float_as_uint(a4.x));
            int p1 = atomicAdd(&g_cursor[d4.y], 1);
            g_edges[p1] = make_uint2((unsigned)s4.y, __float_as_uint(a4.y));
            int p2 = atomicAdd(&g_cursor[d4.z], 1);
            g_edges[p2] = make_uint2((unsigned)s4.z, __float_as_uint(a4.z));
            int p3 = atomicAdd(&g_cursor[d4.w], 1);
            g_edges[p3] = make_uint2((unsigned)s4.w, __float_as_uint(a4.w));
        }
        int tail = E & 3;
        if (tid_g < tail) {
            int e = (E - tail) + tid_g;
            int s = ((const int*)ei)[e];
            int d = ((const int*)ei)[E + e];
            int pos = atomicAdd(&g_cursor[d], 1);
            g_edges[pos] = make_uint2((unsigned)s, __float_as_uint(attr[e]));
        }
    } else {
        for (int e = tid_g; e < E; e += nt) {
            int s = (int)((const long long*)ei)[e];
            int d = (int)((const long long*)ei)[E + e];
            int pos = atomicAdd(&g_cursor[d], 1);
            g_edges[pos] = make_uint2((unsigned)s, __float_as_uint(attr[e]));
        }
    }
    grid_barrier();

    // ---- Phase 4: aggregate. One warp per dest, lane owns 2 cols.
    {
        int lane = tid & 31;
        int w    = tid_g >> 5;
        int nw   = nt >> 5;
        const float* xb = x + lane * 2;

        for (int d = w; d < N; d += nw) {
            int start = g_rowptr[d];
            int deg   = g_deg[d];

            ull a0 = 0, a1 = 0, a2 = 0, a3 = 0;
            int i = 0;
            if (deg > 0 && (start & 1)) {       // peel to 16B-align edge reads
                uint2 e = g_edges[start];
                ull v = *reinterpret_cast<const ull*>(xb + (size_t)e.x * F_XD);
                float wv = __uint_as_float(e.y);
                ffma2(a0, v, pack2(wv, wv));
                i = 1;
            }
            for (; i + 4 <= deg; i += 4) {
                const uint4* ep = (const uint4*)(g_edges + start + i);
                uint4 p0 = ep[0];
                uint4 p1 = ep[1];
                ull v0 = *reinterpret_cast<const ull*>(xb + (size_t)p0.x * F_XD);
                ull v1 = *reinterpret_cast<const ull*>(xb + (size_t)p0.z * F_XD);
                ull v2 = *reinterpret_cast<const ull*>(xb + (size_t)p1.x * F_XD);
                ull v3 = *reinterpret_cast<const ull*>(xb + (size_t)p1.z * F_XD);
                float w0 = __uint_as_float(p0.y), w1 = __uint_as_float(p0.w);
                float w2 = __uint_as_float(p1.y), w3 = __uint_as_float(p1.w);
                ffma2(a0, v0, pack2(w0, w0));
                ffma2(a1, v1, pack2(w1, w1));
                ffma2(a2, v2, pack2(w2, w2));
                ffma2(a3, v3, pack2(w3, w3));
            }
            for (; i < deg; i++) {
                uint2 e = g_edges[start + i];
                ull v = *reinterpret_cast<const ull*>(xb + (size_t)e.x * F_XD);
                float wv = __uint_as_float(e.y);
                ffma2(a0, v, pack2(wv, wv));
            }
            ull s = add2(add2(a0, a1), add2(a2, a3));
            *reinterpret_cast<ull*>(g_agg + (size_t)d * F_XD + lane * 2) = s;
        }
    }
}

// ---------------------------------------------------------------------------
// Fused projection: 64-node tile, 512 threads, f32x2 FMAs (as R4, passing).
// ---------------------------------------------------------------------------
#define AS2 66

__global__ void __launch_bounds__(512)
proj_kernel(const void* __restrict__ batch,
            const float* __restrict__ WK,
            const float* __restrict__ WQ,
            float* __restrict__ out, int N) {
    extern __shared__ float sh[];
    float* sW = sh;                 // [64][256]
    float* sA = sh + 64 * 256;      // [64][AS2]
    __shared__ int sB[64];

    int tid   = threadIdx.x;
    int node0 = blockIdx.x * 64;

    for (int i = tid; i < 64 * 64; i += 512) {
        int k = i >> 6;
        int j = (i & 63) * 4;
        float4 v;
        if (j < 128) v = *reinterpret_cast<const float4*>(WK + k * 128 + j);
        else         v = *reinterpret_cast<const float4*>(WQ + k * 128 + (j - 128));
        *reinterpret_cast<float4*>(sW + k * 256 + j) = v;
    }
    for (int i = tid; i < 64 * 64; i += 512) {
        int n = i >> 6;
        int k = i & 63;
        int gn = node0 + n;
        sA[k * AS2 + n] = (gn < N) ? g_agg[(size_t)gn * F_XD + k] : 0.f;
    }
    if (tid < 64) {
        int gn = node0 + tid;
        int b = 0;
        if (gn < N) {
            if (g_is64) b = (int)((const long long*)batch)[gn];
            else        b = ((const int*)batch)[gn];
        }
        sB[tid] = b;
    }
    __syncthreads();

    int cg = tid & 63;
    int ng = tid >> 6;
    int c0 = cg * 4;
    int n0 = ng * 8;

    ull acc[4][4];
#pragma unroll
    for (int p = 0; p < 4; p++)
#pragma unroll
        for (int c = 0; c < 4; c++) acc[p][c] = 0ull;

#pragma unroll 4
    for (int k = 0; k < 64; k++) {
        float4 w = *reinterpret_cast<const float4*>(sW + k * 256 + c0);
        ull w2[4] = { pack2(w.x, w.x), pack2(w.y, w.y),
                      pack2(w.z, w.z), pack2(w.w, w.w) };
        const float* ar = sA + k * AS2 + n0;
        ull a0 = *reinterpret_cast<const ull*>(ar + 0);
        ull a1 = *reinterpret_cast<const ull*>(ar + 2);
        ull a2 = *reinterpret_cast<const ull*>(ar + 4);
        ull a3 = *reinterpret_cast<const ull*>(ar + 6);
#pragma unroll
        for (int c = 0; c < 4; c++) {
            ffma2(acc[0][c], a0, w2[c]);
            ffma2(acc[1][c], a1, w2[c]);
            ffma2(acc[2][c], a2, w2[c]);
            ffma2(acc[3][c], a3, w2[c]);
        }
    }

    float* outK = out;
    float* outQ = out + (size_t)N * 128;

#pragma unroll
    for (int p = 0; p < 4; p++) {
        int nA = n0 + 2 * p, nB = nA + 1;
        int gA = node0 + nA, gB = node0 + nB;
        float4 uA = *reinterpret_cast<const float4*>(g_U + sB[nA] * 256 + c0);
        float4 uB = *reinterpret_cast<const float4*>(g_U + sB[nB] * 256 + c0);

        float2 f0 = *reinterpret_cast<float2*>(&acc[p][0]);
        float2 f1 = *reinterpret_cast<float2*>(&acc[p][1]);
        float2 f2 = *reinterpret_cast<float2*>(&acc[p][2]);
        float2 f3 = *reinterpret_cast<float2*>(&acc[p][3]);

        float4 wa = make_float4(f0.x + uA.x, f1.x + uA.y, f2.x + uA.z, f3.x + uA.w);
        float4 wb = make_float4(f0.y + uB.x, f1.y + uB.y, f2.y + uB.z, f3.y + uB.w);

        if (c0 < 128) {
            if (gA < N) *reinterpret_cast<float4*>(outK + (size_t)gA * 128 + c0) = wa;
            if (gB < N) *reinterpret_cast<float4*>(outK + (size_t)gB * 128 + c0) = wb;
        } else {
            if (gA < N) *reinterpret_cast<float4*>(outQ + (size_t)gA * 128 + (c0 - 128)) = wa;
            if (gB < N) *reinterpret_cast<float4*>(outQ + (size_t)gB * 128 + (c0 - 128)) = wb;
        }
    }
}

// ---------------------------------------------------------------------------
extern "C" void kernel_launch(void* const* d_in, const int* in_sizes, int n_in,
                              void* d_out, int out_size) {
    const float* x     = (const float*)d_in[0];
    const void*  ei    = d_in[1];
    const float* attr  = (const float*)d_in[2];
    const float* u     = (const float*)d_in[3];
    const void*  batch = d_in[4];
    const float* WK    = (const float*)d_in[5];
    const float* bK    = (const float*)d_in[6];
    const float* WQ    = (const float*)d_in[7];
    const float* bQ    = (const float*)d_in[8];
    float*       out   = (float*)d_out;

    int E = in_sizes[2];
    int N = in_sizes[4];

    persist_kernel<<<PK_CTAS, PK_THREADS>>>(x, ei, attr, u, WK, bK, WQ, bQ, E, N);

    int smem = (64 * 256 + 64 * AS2) * (int)sizeof(float);
    cudaFuncSetAttribute(proj_kernel, cudaFuncAttributeMaxDynamicSharedMemorySize, smem);
    proj_kernel<<<(N + 63) / 64, 512, smem>>>(batch, WK, WQ, out, N);
}